// round 3
// baseline (speedup 1.0000x reference)
#include <cuda_runtime.h>
#include <stdint.h>

#define Kb     256
#define Dd     128
#define KEMAX  256
#define WSLOT  64
#define NROWS  1024          // B*T
#define Ff     1025
#define CSTR   (512*1025)    // channel stride in x and out

typedef unsigned long long ull;

// ---- static device scratch (no runtime allocation) ----
__device__ float g_Weff[(size_t)Kb*KEMAX*KEMAX]; // per-band fused W1@W2, stride KeW
__device__ float g_beff[Kb*KEMAX];               // fused bias (incl 1/ola)
__device__ int   g_nnz[Kb];
__device__ int4  g_inv[1056];                    // per-bin contributing slots
__device__ int   g_deg[1056];
__device__ float g_y[(size_t)Kb*WSLOT*NROWS*4];  // per-(band,bin) partial outputs

// ---- packed fp32x2 helpers (Blackwell) ----
__device__ __forceinline__ ull splat2(float v) {
    ull r; asm("mov.b64 %0, {%1, %1};" : "=l"(r) : "f"(v)); return r;
}
__device__ __forceinline__ void ffma2(ull& d, ull a, ull b) {
    asm("fma.rn.f32x2 %0, %1, %2, %0;" : "+l"(d) : "l"(a), "l"(b));
}
__device__ __forceinline__ void unpack2(ull v, float& lo, float& hi) {
    asm("mov.b64 {%0, %1}, %2;" : "=f"(lo), "=f"(hi) : "l"(v));
}

// ---------------------------------------------------------------------------
// k_meta: per-band nnz + deterministic inverse map bin -> (band,slot) list.
// Mel supports are contiguous bin runs, so membership is a range test.
// ---------------------------------------------------------------------------
__global__ __launch_bounds__(256) void k_meta(
    const int* __restrict__ nzidx, const float* __restrict__ mask, int Wb)
{
    __shared__ int s_flo[Kb], s_nnz[Kb];
    const int k = threadIdx.x;
    int n = 0;
    for (int w = 0; w < Wb; ++w) n += (mask[k*Wb + w] > 0.5f);
    g_nnz[k] = n; s_nnz[k] = n;
    s_flo[k] = nzidx[k*Wb];
    __syncthreads();

    for (int f = k; f < Ff; f += 256) {
        int slots[4] = {0,0,0,0};
        int cnt = 0;
        for (int kk = 0; kk < Kb; ++kk) {
            int w = f - s_flo[kk];
            if (w >= 0 && w < s_nnz[kk]) {
                if (cnt < 4) slots[cnt] = kk*WSLOT + w;
                ++cnt;
            }
        }
        g_inv[f] = make_int4(slots[0], slots[1], slots[2], slots[3]);
        g_deg[f] = min(cnt, 4);
    }
}

// ---------------------------------------------------------------------------
// k_weff: fused per-band weights
//   W_eff[k][i][o] = mel[w_i] * (W1[k][i][:] . W2[k][:][o]) / ola[f(w_o)]
//   b_eff[k][o]    = (b1[k] . W2[k][:,o] + b2[k][o]) / ola[f(w_o)]
// ---------------------------------------------------------------------------
__global__ __launch_bounds__(256) void k_weff(
    const float* __restrict__ W1, const float* __restrict__ b1,
    const float* __restrict__ W2, const float* __restrict__ b2,
    const int*   __restrict__ nzidx, const float* __restrict__ nzmel,
    const float* __restrict__ ola, int Wb)
{
    extern __shared__ __align__(16) float sm[];
    const int k   = blockIdx.x;
    const int KeW = 4*Wb;
    const int iBase = blockIdx.y * 32;

    const int nnz = g_nnz[k];
    const int Ke4 = 4*nnz;
    if (iBase >= Ke4) return;
    const int ni = min(32, Ke4 - iBase);

    float* W1s = sm;                 // [32][128]
    float* W2s = sm + 32*Dd;         // [128][Ke4] compact
    float* rs  = W2s + Dd*KeW;       // mel, size Ke4
    float* cs  = rs + KeW;           // 1/ola, size Ke4

    for (int j = threadIdx.x; j < ni*Dd; j += 256)
        W1s[j] = W1[((size_t)k*KeW + iBase)*Dd + j];
    for (int j = threadIdx.x; j < Dd*Ke4; j += 256) {
        int d = j / Ke4, o = j - d*Ke4;
        W2s[j] = W2[((size_t)k*Dd + d)*KeW + o];
    }
    for (int w = threadIdx.x; w < nnz; w += 256) {
        float m   = nzmel[k*Wb + w];
        float inv = 1.0f / ola[nzidx[k*Wb + w]];
        rs[4*w+0]=m;   rs[4*w+1]=m;   rs[4*w+2]=m;   rs[4*w+3]=m;
        cs[4*w+0]=inv; cs[4*w+1]=inv; cs[4*w+2]=inv; cs[4*w+3]=inv;
    }
    __syncthreads();

    const int nrt = ni >> 2, nct = Ke4 >> 2;
    for (int tile = threadIdx.x; tile < nrt*nct; tile += 256) {
        int tr = tile / nct, tc = tile - tr*nct;
        float acc[4][4] = {};
        const float* a  = &W1s[(tr*4)*Dd];
        const float* bp = &W2s[tc*4];
        for (int d = 0; d < Dd; ++d) {
            float a0 = a[d], a1 = a[Dd+d], a2 = a[2*Dd+d], a3 = a[3*Dd+d];
            float4 bv = *reinterpret_cast<const float4*>(bp); bp += Ke4;
            acc[0][0]+=a0*bv.x; acc[0][1]+=a0*bv.y; acc[0][2]+=a0*bv.z; acc[0][3]+=a0*bv.w;
            acc[1][0]+=a1*bv.x; acc[1][1]+=a1*bv.y; acc[1][2]+=a1*bv.z; acc[1][3]+=a1*bv.w;
            acc[2][0]+=a2*bv.x; acc[2][1]+=a2*bv.y; acc[2][2]+=a2*bv.z; acc[2][3]+=a2*bv.w;
            acc[3][0]+=a3*bv.x; acc[3][1]+=a3*bv.y; acc[3][2]+=a3*bv.z; acc[3][3]+=a3*bv.w;
        }
        int gi = iBase + tr*4, go = tc*4;
        #pragma unroll
        for (int rr = 0; rr < 4; ++rr) {
            float rsc = rs[gi+rr];
            #pragma unroll
            for (int oo = 0; oo < 4; ++oo)
                g_Weff[((size_t)k*KeW + gi+rr)*KeW + go+oo] = rsc*cs[go+oo]*acc[rr][oo];
        }
    }

    if (blockIdx.y == 0) {
        for (int o = threadIdx.x; o < Ke4; o += 256) {
            float s = b2[(size_t)k*KeW + o];
            for (int d = 0; d < Dd; ++d) s += b1[k*Dd + d] * W2s[d*Ke4 + o];
            g_beff[k*KEMAX + o] = s * cs[o];
        }
    }
}

// ---------------------------------------------------------------------------
// k_main: per-(band, 128 rows) GEMM, packed f32x2 math, rows paired in smem.
//   A gathered directly from x (contiguous bins -> coalesced).
//   W_eff streamed from L2 (uniform LDG.128 per warp).
//   Output: plain float4 stores into g_y[(k,w)][row][4].
// ---------------------------------------------------------------------------
__global__ __launch_bounds__(256) void k_main(
    const float* __restrict__ x, const int* __restrict__ nzidx, int Wb)
{
    extern __shared__ __align__(16) ull As2[];  // [64 rowpairs][Ke4] packed float2
    __shared__ int sidx[WSLOT];

    const int k   = blockIdx.x;
    const int r0  = blockIdx.y * 128;
    const int nnz = g_nnz[k];
    const int Ke4 = 4*nnz;
    const int KeW = 4*Wb;
    const int tid = threadIdx.x;
    const int tx  = tid & 15, ty = tid >> 4;

    if (tid < nnz) sidx[tid] = nzidx[k*Wb + tid];
    __syncthreads();

    // gather A: value(row, i=4w+c) = x[b][c][t][f(w)], packed as row pairs
    float* Af = reinterpret_cast<float*>(As2);
    const int tot = 128*nnz;
    for (int p = tid; p < tot; p += 256) {
        int lr = p / nnz, w = p - lr*nnz;
        int f = sidx[w];
        int row = r0 + lr, b = row >> 9, t = row & 511;
        const float* xb = x + ((size_t)b*4*512 + t)*Ff + f;
        int rp = lr >> 1, par = lr & 1;
        int base = (rp*Ke4 + 4*w)*2 + par;
        Af[base + 0] = xb[0];
        Af[base + 2] = xb[(size_t)CSTR];
        Af[base + 4] = xb[(size_t)2*CSTR];
        Af[base + 6] = xb[(size_t)3*CSTR];
    }
    __syncthreads();

    const float* Wk = g_Weff + (size_t)k*KeW*KeW;
    const int ncg = (nnz + 15) >> 4;

    for (int cg = 0; cg < ncg; ++cg) {
        const int wth = cg*16 + tx;
        if (wth >= nnz) continue;
        const int col = wth*4;

        ull acc[4][4];
        #pragma unroll
        for (int rp = 0; rp < 4; ++rp)
            #pragma unroll
            for (int c = 0; c < 4; ++c) acc[rp][c] = 0ULL;

        #pragma unroll 2
        for (int ke4 = 0; ke4 < Ke4; ke4 += 4) {
            const float* wp = Wk + (size_t)ke4*KeW + col;
            float4 w0 = *reinterpret_cast<const float4*>(wp);
            float4 w1 = *reinterpret_cast<const float4*>(wp + KeW);
            float4 w2 = *reinterpret_cast<const float4*>(wp + 2*KeW);
            float4 w3 = *reinterpret_cast<const float4*>(wp + 3*KeW);

            ull ws[4][4];
            ws[0][0]=splat2(w0.x); ws[0][1]=splat2(w0.y); ws[0][2]=splat2(w0.z); ws[0][3]=splat2(w0.w);
            ws[1][0]=splat2(w1.x); ws[1][1]=splat2(w1.y); ws[1][2]=splat2(w1.z); ws[1][3]=splat2(w1.w);
            ws[2][0]=splat2(w2.x); ws[2][1]=splat2(w2.y); ws[2][2]=splat2(w2.z); ws[2][3]=splat2(w2.w);
            ws[3][0]=splat2(w3.x); ws[3][1]=splat2(w3.y); ws[3][2]=splat2(w3.z); ws[3][3]=splat2(w3.w);

            #pragma unroll
            for (int rp = 0; rp < 4; ++rp) {
                const ulonglong2* ap = reinterpret_cast<const ulonglong2*>(
                    &As2[(size_t)(ty*4 + rp)*Ke4 + ke4]);
                ulonglong2 a01 = ap[0];
                ulonglong2 a23 = ap[1];
                #pragma unroll
                for (int c = 0; c < 4; ++c) ffma2(acc[rp][c], a01.x, ws[0][c]);
                #pragma unroll
                for (int c = 0; c < 4; ++c) ffma2(acc[rp][c], a01.y, ws[1][c]);
                #pragma unroll
                for (int c = 0; c < 4; ++c) ffma2(acc[rp][c], a23.x, ws[2][c]);
                #pragma unroll
                for (int c = 0; c < 4; ++c) ffma2(acc[rp][c], a23.y, ws[3][c]);
            }
        }

        // epilogue: add bias, store both rows of each pair
        float4 bv = *reinterpret_cast<const float4*>(&g_beff[k*KEMAX + col]);
        size_t ybase = (size_t)(k*WSLOT + wth) * NROWS;
        #pragma unroll
        for (int rp = 0; rp < 4; ++rp) {
            float l0,h0,l1,h1,l2,h2,l3,h3;
            unpack2(acc[rp][0], l0, h0);
            unpack2(acc[rp][1], l1, h1);
            unpack2(acc[rp][2], l2, h2);
            unpack2(acc[rp][3], l3, h3);
            int rowp = r0 + (ty*4 + rp)*2;
            float4 o0 = make_float4(l0+bv.x, l1+bv.y, l2+bv.z, l3+bv.w);
            float4 o1 = make_float4(h0+bv.x, h1+bv.y, h2+bv.z, h3+bv.w);
            *reinterpret_cast<float4*>(&g_y[(ybase + rowp  )*4]) = o0;
            *reinterpret_cast<float4*>(&g_y[(ybase + rowp+1)*4]) = o1;
        }
    }
}

// ---------------------------------------------------------------------------
// k_gout: gather-reduce per bin + transpose to (B,C2,T,F). Fully coalesced.
// ---------------------------------------------------------------------------
__global__ __launch_bounds__(256) void k_gout(float* __restrict__ out)
{
    __shared__ float sm[4][32][33];
    const int f0 = blockIdx.x * 32;
    const int r0 = blockIdx.y * 32;
    const int tid = threadIdx.x;
    const int rx = tid & 31, ry = tid >> 5;

    #pragma unroll
    for (int q = 0; q < 4; ++q) {
        int fl = ry*4 + q;
        int f = f0 + fl;
        float4 acc = make_float4(0.f, 0.f, 0.f, 0.f);
        if (f < Ff) {
            int4 iv = g_inv[f];
            int dg = g_deg[f];
            int sl[4] = {iv.x, iv.y, iv.z, iv.w};
            for (int j = 0; j < dg; ++j) {
                float4 v = *reinterpret_cast<const float4*>(
                    &g_y[((size_t)sl[j]*NROWS + r0 + rx)*4]);
                acc.x += v.x; acc.y += v.y; acc.z += v.z; acc.w += v.w;
            }
        }
        sm[0][fl][rx] = acc.x; sm[1][fl][rx] = acc.y;
        sm[2][fl][rx] = acc.z; sm[3][fl][rx] = acc.w;
    }
    __syncthreads();

    const int fx = tid & 31, g = tid >> 5;
    const int f = f0 + fx;
    if (f < Ff) {
        #pragma unroll
        for (int it = 0; it < 16; ++it) {
            int idx = g*16 + it;
            int c = idx >> 5, rowl = idx & 31;
            int row = r0 + rowl, b = row >> 9, t = row & 511;
            out[((size_t)(b*4 + c)*512 + t)*Ff + f] = sm[c][fx][rowl];
        }
    }
}

// ---------------------------------------------------------------------------
extern "C" void kernel_launch(void* const* d_in, const int* in_sizes, int n_in,
                              void* d_out, int out_size)
{
    const float* x     = (const float*)d_in[0];
    const float* W1    = (const float*)d_in[1];
    const float* b1    = (const float*)d_in[2];
    const float* W2    = (const float*)d_in[3];
    const float* b2    = (const float*)d_in[4];
    const int*   nzidx = (const int*)  d_in[5];
    const float* nzmel = (const float*)d_in[6];
    const float* mask  = (const float*)d_in[7];
    const float* ola   = (const float*)d_in[8];

    const int Wb  = in_sizes[5] / Kb;
    const int KeW = 4*Wb;

    k_meta<<<1, 256>>>(nzidx, mask, Wb);

    int weff_smem = (32*Dd + Dd*KeW + 2*KeW) * (int)sizeof(float);
    cudaFuncSetAttribute(k_weff, cudaFuncAttributeMaxDynamicSharedMemorySize, weff_smem);
    k_weff<<<dim3(Kb, (KeW + 31)/32), 256, weff_smem>>>(W1, b1, W2, b2,
                                                        nzidx, nzmel, ola, Wb);

    int main_smem = 64 * KeW * (int)sizeof(ull);
    cudaFuncSetAttribute(k_main, cudaFuncAttributeMaxDynamicSharedMemorySize, main_smem);
    k_main<<<dim3(Kb, NROWS/128), 256, main_smem>>>(x, nzidx, Wb);

    k_gout<<<dim3((Ff + 31)/32, NROWS/32), 256>>>((float*)d_out);
}

// round 4
// speedup vs baseline: 1.1451x; 1.1451x over previous
#include <cuda_runtime.h>
#include <stdint.h>

#define Kb     256
#define Dd     128
#define KEMAX  256
#define Ff     1025
#define NROWS  1024
#define CSTR   (512*1025)
#define MW     96          // M row stride in 4x4 blocks
#define NFP    1056        // padded f' count
#define NPAIR  528

typedef unsigned long long ull;

// ---- static device scratch ----
__device__ float g_Weff[(size_t)Kb*KEMAX*KEMAX]; // per-band fused W1@W2 (stride KeW)
__device__ float g_beff[Kb*KEMAX];
__device__ int   g_flo[Kb], g_nz[Kb];
__device__ int   g_deg[NFP], g_bands[NFP*4];
__device__ int   g_fmf[NFP], g_fxf[NFP];
__device__ int   g_fmin2[NPAIR], g_wid2[NPAIR];
__device__ float g_M[(size_t)NFP*MW*16];         // [f'][j][c][c2]
__device__ float g_bias[NFP*4];

__device__ __forceinline__ ull splat2(float v) {
    ull r; asm("mov.b64 %0, {%1, %1};" : "=l"(r) : "f"(v)); return r;
}
__device__ __forceinline__ void ffma2(ull& d, ull a, ull b) {
    asm("fma.rn.f32x2 %0, %1, %2, %0;" : "+l"(d) : "l"(a), "l"(b));
}
__device__ __forceinline__ void unpack2(ull v, float& lo, float& hi) {
    asm("mov.b64 {%0, %1}, %2;" : "=f"(lo), "=f"(hi) : "l"(v));
}

// ---------------------------------------------------------------------------
// k_meta: band ranges; per-f' band list; per-pair fmin/width.
// ---------------------------------------------------------------------------
__global__ __launch_bounds__(256) void k_meta(
    const int* __restrict__ nzidx, const float* __restrict__ mask, int Wb)
{
    __shared__ int s_flo[Kb], s_nnz[Kb];
    const int tid = threadIdx.x;
    {
        int n = 0;
        for (int w = 0; w < Wb; ++w) n += (mask[tid*Wb + w] > 0.5f);
        int flo = nzidx[tid*Wb];
        s_flo[tid] = flo; s_nnz[tid] = n;
        g_flo[tid] = flo; g_nz[tid] = n;
    }
    __syncthreads();
    for (int f = tid; f < NFP; f += 256) {
        int deg = 0, bl[4] = {0,0,0,0};
        int fmn = 1<<29, fmx = -1;
        if (f < Ff) {
            for (int k = 0; k < Kb; ++k) {
                int w = f - s_flo[k];
                if (w >= 0 && w < s_nnz[k]) {
                    if (deg < 4) bl[deg] = k;
                    ++deg;
                    fmn = min(fmn, s_flo[k]);
                    fmx = max(fmx, s_flo[k] + s_nnz[k]);
                }
            }
        }
        deg = min(deg, 4);
        g_deg[f] = deg;
        #pragma unroll
        for (int i = 0; i < 4; ++i) g_bands[f*4+i] = bl[i];
        g_fmf[f] = deg ? fmn : 0;
        g_fxf[f] = deg ? fmx : 0;
    }
    __syncthreads();
    for (int p = tid; p < NPAIR; p += 256) {
        int fmn = 1<<29, fmx = -1;
        #pragma unroll
        for (int s = 0; s < 2; ++s) {
            int f = 2*p + s;
            if (f < Ff && g_deg[f] > 0) {
                fmn = min(fmn, g_fmf[f]);
                fmx = max(fmx, g_fxf[f]);
            }
        }
        if (fmx < 0) { g_fmin2[p] = 0; g_wid2[p] = 0; }
        else { g_fmin2[p] = fmn; g_wid2[p] = min(fmx - fmn, MW); }
    }
}

// ---------------------------------------------------------------------------
// k_weff: per-band fused weights (mel, 1/ola, biases folded). grid (Kb, 2).
// ---------------------------------------------------------------------------
__global__ __launch_bounds__(256) void k_weff(
    const float* __restrict__ W1, const float* __restrict__ b1,
    const float* __restrict__ W2, const float* __restrict__ b2,
    const int*   __restrict__ nzidx, const float* __restrict__ nzmel,
    const float* __restrict__ ola, int Wb)
{
    extern __shared__ __align__(16) float sm[];
    const int k     = blockIdx.x;
    const int KeW   = 4*Wb;
    const int iBase = blockIdx.y * 68;

    const int nnz = g_nz[k];
    const int Ke4 = 4*nnz;
    if (iBase >= Ke4) return;
    const int ni = min(68, Ke4 - iBase);

    float* W1s = sm;                 // [68][128]
    float* W2s = sm + 68*Dd;         // [128][Ke4]
    float* rs  = W2s + Dd*KeW;       // mel
    float* cs  = rs + KeW;           // 1/ola

    for (int j = threadIdx.x; j < ni*Dd; j += 256)
        W1s[j] = W1[((size_t)k*KeW + iBase)*Dd + j];
    for (int j = threadIdx.x; j < Dd*Ke4; j += 256) {
        int d = j / Ke4, o = j - d*Ke4;
        W2s[j] = W2[((size_t)k*Dd + d)*KeW + o];
    }
    for (int w = threadIdx.x; w < nnz; w += 256) {
        float m   = nzmel[k*Wb + w];
        float inv = 1.0f / ola[nzidx[k*Wb + w]];
        rs[4*w+0]=m;   rs[4*w+1]=m;   rs[4*w+2]=m;   rs[4*w+3]=m;
        cs[4*w+0]=inv; cs[4*w+1]=inv; cs[4*w+2]=inv; cs[4*w+3]=inv;
    }
    __syncthreads();

    const int nrt = ni >> 2, nct = Ke4 >> 2;
    for (int tile = threadIdx.x; tile < nrt*nct; tile += 256) {
        int tr = tile / nct, tc = tile - tr*nct;
        float acc[4][4] = {};
        const float* a  = &W1s[(tr*4)*Dd];
        const float* bp = &W2s[tc*4];
        for (int d = 0; d < Dd; ++d) {
            float a0 = a[d], a1 = a[Dd+d], a2 = a[2*Dd+d], a3 = a[3*Dd+d];
            float4 bv = *reinterpret_cast<const float4*>(bp); bp += Ke4;
            acc[0][0]+=a0*bv.x; acc[0][1]+=a0*bv.y; acc[0][2]+=a0*bv.z; acc[0][3]+=a0*bv.w;
            acc[1][0]+=a1*bv.x; acc[1][1]+=a1*bv.y; acc[1][2]+=a1*bv.z; acc[1][3]+=a1*bv.w;
            acc[2][0]+=a2*bv.x; acc[2][1]+=a2*bv.y; acc[2][2]+=a2*bv.z; acc[2][3]+=a2*bv.w;
            acc[3][0]+=a3*bv.x; acc[3][1]+=a3*bv.y; acc[3][2]+=a3*bv.z; acc[3][3]+=a3*bv.w;
        }
        int gi = iBase + tr*4, go = tc*4;
        #pragma unroll
        for (int rr = 0; rr < 4; ++rr) {
            float rsc = rs[gi+rr];
            #pragma unroll
            for (int oo = 0; oo < 4; ++oo)
                g_Weff[((size_t)k*KeW + gi+rr)*KeW + go+oo] = rsc*cs[go+oo]*acc[rr][oo];
        }
    }

    if (blockIdx.y == 0) {
        for (int o = threadIdx.x; o < Ke4; o += 256) {
            float s = b2[(size_t)k*KeW + o];
            for (int d = 0; d < Dd; ++d) s += b1[k*Dd + d] * W2s[d*Ke4 + o];
            g_beff[k*KEMAX + o] = s * cs[o];
        }
    }
}

// ---------------------------------------------------------------------------
// k_scatter: assemble banded matrix rows. 1 block per f' (deterministic).
//   M[f'][j][c][c2] = sum over bands k containing both f'=bin(w') and
//                     f=fmin2+j=bin(w) of g_Weff[k][4w+c][4w'+c2]
// ---------------------------------------------------------------------------
__global__ __launch_bounds__(256) void k_scatter(int Wb)
{
    const int f   = blockIdx.x;
    const int KeW = 4*Wb;
    const int p   = f >> 1;
    const int fm2 = g_fmin2[p];
    const int deg = g_deg[f];
    __shared__ int s_k[4], s_flo[4], s_nnz[4], s_wp[4];
    if (threadIdx.x < 4) {
        int k = g_bands[f*4 + threadIdx.x];
        s_k[threadIdx.x]   = k;
        s_flo[threadIdx.x] = g_flo[k];
        s_nnz[threadIdx.x] = g_nz[k];
        s_wp[threadIdx.x]  = f - g_flo[k];
    }
    __syncthreads();

    for (int pos = threadIdx.x; pos < MW*16; pos += 256) {
        int j  = pos >> 4;
        int cc = pos & 15;
        int c  = cc >> 2, c2 = cc & 3;
        int fbin = fm2 + j;
        float v = 0.0f;
        for (int d = 0; d < deg; ++d) {
            int w = fbin - s_flo[d];
            if (w >= 0 && w < s_nnz[d]) {
                int k = s_k[d], wp = s_wp[d];
                v += g_Weff[((size_t)k*KeW + 4*w + c)*KeW + 4*wp + c2];
            }
        }
        g_M[((size_t)f*MW + j)*16 + cc] = v;
    }
    if (threadIdx.x < 4) {
        float v = 0.0f;
        for (int d = 0; d < deg; ++d)
            v += g_beff[s_k[d]*KEMAX + 4*s_wp[d] + threadIdx.x];
        g_bias[f*4 + threadIdx.x] = v;
    }
}

// ---------------------------------------------------------------------------
// k_main: block = 64 rows x 16 f'. warp = 32 lanes (2 rows each) x 1 f'-pair.
// M loads warp-uniform (L2 broadcast); x from padded smem; FFMA2 math.
// Writes d_out directly (smem-staged, coalesced).
// ---------------------------------------------------------------------------
__global__ __launch_bounds__(256, 2) void k_main(
    const float* __restrict__ x, float* __restrict__ out, int xrange, int xw)
{
    extern __shared__ __align__(16) float4 smx[];          // [64][xw]
    float* smo = reinterpret_cast<float*>(smx + 64*xw);    // [64][4][16]

    const int tid  = threadIdx.x;
    const int f0   = blockIdx.x * 16;
    const int p0   = f0 >> 1;
    const int row0 = blockIdx.y * 64;
    const int fbase = g_fmin2[p0];

    // stage x tile: [r][u] -> float4 over c
    for (int e = tid; e < 64*xrange; e += 256) {
        int u = e % xrange, r = e / xrange;
        int f = min(fbase + u, Ff-1);
        int row = row0 + r, b = row >> 9, t = row & 511;
        const float* xp = x + ((size_t)(b*4)*512 + t)*Ff + f;
        smx[r*xw + u] = make_float4(xp[0], xp[CSTR], xp[(size_t)2*CSTR], xp[(size_t)3*CSTR]);
    }
    __syncthreads();

    const int wid = tid >> 5, lane = tid & 31;
    const int p   = p0 + wid;
    const int jmax = g_wid2[p];
    const int u0   = g_fmin2[p] - fbase;
    const int fA   = 2*p;

    const ulonglong2* mA = reinterpret_cast<const ulonglong2*>(g_M + (size_t)fA*MW*16);
    const ulonglong2* mB = reinterpret_cast<const ulonglong2*>(g_M + (size_t)(fA+1)*MW*16);
    ulonglong2 bA = *reinterpret_cast<const ulonglong2*>(&g_bias[fA*4]);
    ulonglong2 bB = *reinterpret_cast<const ulonglong2*>(&g_bias[(fA+1)*4]);

    ull acc[2][2][2];
    #pragma unroll
    for (int r2 = 0; r2 < 2; ++r2) {
        acc[r2][0][0] = bA.x; acc[r2][0][1] = bA.y;
        acc[r2][1][0] = bB.x; acc[r2][1][1] = bB.y;
    }

    const float4* xpA = smx + lane*xw + u0;
    const float4* xpB = smx + (lane+32)*xw + u0;

    #pragma unroll 2
    for (int j = 0; j < jmax; ++j) {
        float4 xa = xpA[j];
        float4 xb = xpB[j];
        ulonglong2 a0 = mA[j*4+0], a1 = mA[j*4+1], a2 = mA[j*4+2], a3 = mA[j*4+3];
        ulonglong2 c0 = mB[j*4+0], c1 = mB[j*4+1], c2v = mB[j*4+2], c3 = mB[j*4+3];
        ull s;
        s = splat2(xa.x);
        ffma2(acc[0][0][0], s, a0.x); ffma2(acc[0][0][1], s, a0.y);
        ffma2(acc[0][1][0], s, c0.x); ffma2(acc[0][1][1], s, c0.y);
        s = splat2(xa.y);
        ffma2(acc[0][0][0], s, a1.x); ffma2(acc[0][0][1], s, a1.y);
        ffma2(acc[0][1][0], s, c1.x); ffma2(acc[0][1][1], s, c1.y);
        s = splat2(xa.z);
        ffma2(acc[0][0][0], s, a2.x); ffma2(acc[0][0][1], s, a2.y);
        ffma2(acc[0][1][0], s, c2v.x); ffma2(acc[0][1][1], s, c2v.y);
        s = splat2(xa.w);
        ffma2(acc[0][0][0], s, a3.x); ffma2(acc[0][0][1], s, a3.y);
        ffma2(acc[0][1][0], s, c3.x); ffma2(acc[0][1][1], s, c3.y);

        s = splat2(xb.x);
        ffma2(acc[1][0][0], s, a0.x); ffma2(acc[1][0][1], s, a0.y);
        ffma2(acc[1][1][0], s, c0.x); ffma2(acc[1][1][1], s, c0.y);
        s = splat2(xb.y);
        ffma2(acc[1][0][0], s, a1.x); ffma2(acc[1][0][1], s, a1.y);
        ffma2(acc[1][1][0], s, c1.x); ffma2(acc[1][1][1], s, c1.y);
        s = splat2(xb.z);
        ffma2(acc[1][0][0], s, a2.x); ffma2(acc[1][0][1], s, a2.y);
        ffma2(acc[1][1][0], s, c2v.x); ffma2(acc[1][1][1], s, c2v.y);
        s = splat2(xb.w);
        ffma2(acc[1][0][0], s, a3.x); ffma2(acc[1][0][1], s, a3.y);
        ffma2(acc[1][1][0], s, c3.x); ffma2(acc[1][1][1], s, c3.y);
    }

    // stage results: smo[r][c2][fx]
    #pragma unroll
    for (int r2 = 0; r2 < 2; ++r2) {
        int r = lane + r2*32;
        #pragma unroll
        for (int g = 0; g < 2; ++g) {
            int fx = 2*wid + g;
            float v0, v1, v2, v3;
            unpack2(acc[r2][g][0], v0, v1);
            unpack2(acc[r2][g][1], v2, v3);
            smo[(r*4 + 0)*16 + fx] = v0;
            smo[(r*4 + 1)*16 + fx] = v1;
            smo[(r*4 + 2)*16 + fx] = v2;
            smo[(r*4 + 3)*16 + fx] = v3;
        }
    }
    __syncthreads();

    // coalesced store
    for (int e = tid; e < 4096; e += 256) {
        int fx = e & 15, cc2 = (e >> 4) & 3, r = e >> 6;
        int f = f0 + fx;
        if (f < Ff) {
            int row = row0 + r, b = row >> 9, t = row & 511;
            out[((size_t)(b*4 + cc2)*512 + t)*Ff + f] = smo[(r*4 + cc2)*16 + fx];
        }
    }
}

// ---------------------------------------------------------------------------
extern "C" void kernel_launch(void* const* d_in, const int* in_sizes, int n_in,
                              void* d_out, int out_size)
{
    const float* x     = (const float*)d_in[0];
    const float* W1    = (const float*)d_in[1];
    const float* b1    = (const float*)d_in[2];
    const float* W2    = (const float*)d_in[3];
    const float* b2    = (const float*)d_in[4];
    const int*   nzidx = (const int*)  d_in[5];
    const float* nzmel = (const float*)d_in[6];
    const float* mask  = (const float*)d_in[7];
    const float* ola   = (const float*)d_in[8];

    const int Wb  = in_sizes[5] / Kb;
    const int KeW = 4*Wb;

    k_meta<<<1, 256>>>(nzidx, mask, Wb);

    int weff_smem = (68*Dd + Dd*KeW + 2*KeW) * (int)sizeof(float);
    cudaFuncSetAttribute(k_weff, cudaFuncAttributeMaxDynamicSharedMemorySize, weff_smem);
    k_weff<<<dim3(Kb, 2), 256, weff_smem>>>(W1, b1, W2, b2, nzidx, nzmel, ola, Wb);

    k_scatter<<<NFP, 256>>>(Wb);

    int xrange = 2*Wb + 16;
    int xw = xrange | 1;
    int main_smem = 64*xw*(int)sizeof(float4) + 4096*(int)sizeof(float);
    cudaFuncSetAttribute(k_main, cudaFuncAttributeMaxDynamicSharedMemorySize, main_smem);
    k_main<<<dim3((Ff + 15)/16, NROWS/64), 256, main_smem>>>(x, (float*)d_out, xrange, xw);
}

// round 5
// speedup vs baseline: 1.4960x; 1.3065x over previous
#include <cuda_runtime.h>
#include <stdint.h>

#define Kb     256
#define Dd     128
#define KEMAX  256
#define Ff     1025
#define NROWS  1024
#define CSTR   (512*1025)
#define MW     96
#define NFP    1056
#define NPAIR  528

typedef unsigned long long ull;

// ---- static device scratch ----
__device__ float g_Weff[(size_t)Kb*KEMAX*KEMAX];
__device__ float g_beff[Kb*KEMAX];
__device__ int   g_flo[Kb], g_nz[Kb];
__device__ int   g_deg[NFP], g_bands[NFP*4];
__device__ int   g_fmin2[NPAIR], g_wid2[NPAIR];
__device__ float g_M[(size_t)NFP*MW*16];   // [f'][j][c][c2]
__device__ float g_bias[NFP*4];

__device__ __forceinline__ ull splat2(float v) {
    ull r; asm("mov.b64 %0, {%1, %1};" : "=l"(r) : "f"(v)); return r;
}
__device__ __forceinline__ void ffma2(ull& d, ull a, ull b) {
    asm("fma.rn.f32x2 %0, %1, %2, %0;" : "+l"(d) : "l"(a), "l"(b));
}
__device__ __forceinline__ void unpack2(ull v, float& lo, float& hi) {
    asm("mov.b64 {%0, %1}, %2;" : "=f"(lo), "=f"(hi) : "l"(v));
}

// ---------------------------------------------------------------------------
// k_bands: per-band first bin + nnz. 1 small block.
// ---------------------------------------------------------------------------
__global__ __launch_bounds__(256) void k_bands(
    const int* __restrict__ nzidx, const float* __restrict__ mask, int Wb)
{
    const int k = threadIdx.x;
    int n = 0;
    for (int w = 0; w < Wb; ++w) n += (mask[k*Wb + w] > 0.5f);
    g_flo[k] = nzidx[k*Wb];
    g_nz[k]  = n;
}

// ---------------------------------------------------------------------------
// k_finfo: per-f' band list + per-pair [fmin,width). 33 parallel blocks.
// ---------------------------------------------------------------------------
__global__ __launch_bounds__(256) void k_finfo()
{
    __shared__ int s_flo[Kb], s_nz[Kb];
    __shared__ int s_fmf[32], s_fxf[32];
    const int tid = threadIdx.x;
    s_flo[tid] = g_flo[tid];
    s_nz[tid]  = g_nz[tid];
    __syncthreads();

    if (tid < 32) {
        int f = blockIdx.x*32 + tid;
        int deg = 0, bl[4] = {0,0,0,0};
        int fmn = 1<<29, fmx = -1;
        if (f < Ff) {
            for (int k = 0; k < Kb; ++k) {
                int w = f - s_flo[k];
                if (w >= 0 && w < s_nz[k]) {
                    if (deg < 4) bl[deg] = k;
                    ++deg;
                    fmn = min(fmn, s_flo[k]);
                    fmx = max(fmx, s_flo[k] + s_nz[k]);
                }
            }
        }
        deg = min(deg, 4);
        if (f < NFP) {
            g_deg[f] = deg;
            #pragma unroll
            for (int i = 0; i < 4; ++i) g_bands[f*4+i] = bl[i];
        }
        s_fmf[tid] = deg ? fmn : (1<<29);
        s_fxf[tid] = deg ? fmx : -1;
    }
    __syncthreads();
    if (tid < 16) {
        int p = blockIdx.x*16 + tid;
        int fmn = min(s_fmf[2*tid], s_fmf[2*tid+1]);
        int fmx = max(s_fxf[2*tid], s_fxf[2*tid+1]);
        if (p < NPAIR) {
            if (fmx < 0) { g_fmin2[p] = 0; g_wid2[p] = 0; }
            else         { g_fmin2[p] = fmn; g_wid2[p] = min(fmx - fmn, MW); }
        }
    }
}

// ---------------------------------------------------------------------------
// k_weff: per-band fused W1@W2 (mel, 1/ola folded). grid (Kb, itiles of 16).
// W1 rows in smem (reused across all column tiles), W2 via coalesced LDG
// (L1-cached). One 4x4 tile per thread, f32x2 math.
// ---------------------------------------------------------------------------
__global__ __launch_bounds__(256) void k_weff(
    const float* __restrict__ W1, const float* __restrict__ b1,
    const float* __restrict__ W2, const float* __restrict__ b2,
    const int*   __restrict__ nzidx, const float* __restrict__ nzmel,
    const float* __restrict__ ola, int Wb)
{
    __shared__ float W1s[16*Dd];
    __shared__ float cs[KEMAX];
    __shared__ float rs[16];
    __shared__ float b1s[Dd];

    const int k     = blockIdx.x;
    const int KeW   = 4*Wb;
    const int iBase = blockIdx.y * 16;
    const int tid   = threadIdx.x;

    const int nnz = g_nz[k];
    const int Ke4 = 4*nnz;
    if (iBase >= Ke4) return;
    const int ni = min(16, Ke4 - iBase);

    for (int j = tid; j < ni*Dd; j += 256)
        W1s[j] = W1[((size_t)k*KeW + iBase)*Dd + j];
    for (int w = tid; w < nnz; w += 256) {
        float inv = 1.0f / ola[nzidx[k*Wb + w]];
        cs[4*w+0]=inv; cs[4*w+1]=inv; cs[4*w+2]=inv; cs[4*w+3]=inv;
    }
    if (tid < ni) rs[tid] = nzmel[k*Wb + ((iBase + tid) >> 2)];
    if (tid < Dd) b1s[tid] = b1[k*Dd + tid];
    __syncthreads();

    const int nct = Ke4 >> 2, nrt = ni >> 2;
    if (tid < nrt*nct) {
        const int tr = tid / nct, tc = tid - tr*nct;
        ull acc[4][2] = {{0,0},{0,0},{0,0},{0,0}};
        const float* a = &W1s[(tr*4)*Dd];
        const float* w2base = W2 + (size_t)k*Dd*KeW + tc*4;
        #pragma unroll 4
        for (int d = 0; d < Dd; ++d) {
            ulonglong2 bv = *reinterpret_cast<const ulonglong2*>(w2base + (size_t)d*KeW);
            ull s;
            s = splat2(a[d]);      ffma2(acc[0][0], s, bv.x); ffma2(acc[0][1], s, bv.y);
            s = splat2(a[Dd+d]);   ffma2(acc[1][0], s, bv.x); ffma2(acc[1][1], s, bv.y);
            s = splat2(a[2*Dd+d]); ffma2(acc[2][0], s, bv.x); ffma2(acc[2][1], s, bv.y);
            s = splat2(a[3*Dd+d]); ffma2(acc[3][0], s, bv.x); ffma2(acc[3][1], s, bv.y);
        }
        const int gi = iBase + tr*4, go = tc*4;
        float4 c4 = *reinterpret_cast<const float4*>(&cs[go]);
        #pragma unroll
        for (int rr = 0; rr < 4; ++rr) {
            float v0,v1,v2,v3;
            unpack2(acc[rr][0], v0, v1);
            unpack2(acc[rr][1], v2, v3);
            float r = rs[tr*4+rr];
            float4 o4 = make_float4(v0*r*c4.x, v1*r*c4.y, v2*r*c4.z, v3*r*c4.w);
            *reinterpret_cast<float4*>(&g_Weff[((size_t)k*KeW + gi+rr)*KeW + go]) = o4;
        }
    }

    if (blockIdx.y == 0) {
        for (int o = tid; o < Ke4; o += 256) {
            float s = b2[(size_t)k*KeW + o];
            for (int d = 0; d < Dd; ++d) s += b1s[d] * W2[((size_t)k*Dd + d)*KeW + o];
            g_beff[k*KEMAX + o] = s * cs[o];
        }
    }
}

// ---------------------------------------------------------------------------
// k_scatter: assemble banded rows of M (only the live wid2 range).
// ---------------------------------------------------------------------------
__global__ __launch_bounds__(256) void k_scatter(int Wb)
{
    const int f   = blockIdx.x;
    const int KeW = 4*Wb;
    const int p   = f >> 1;
    const int fm2 = g_fmin2[p];
    const int wid = g_wid2[p];
    const int deg = g_deg[f];
    __shared__ int s_k[4], s_flo4[4], s_nz4[4], s_wp[4];
    if (threadIdx.x < 4) {
        int k = g_bands[f*4 + threadIdx.x];
        s_k[threadIdx.x]    = k;
        s_flo4[threadIdx.x] = g_flo[k];
        s_nz4[threadIdx.x]  = g_nz[k];
        s_wp[threadIdx.x]   = f - g_flo[k];
    }
    __syncthreads();

    for (int pos = threadIdx.x; pos < wid*16; pos += 256) {
        int j  = pos >> 4;
        int cc = pos & 15;
        int c  = cc >> 2, c2 = cc & 3;
        int fbin = fm2 + j;
        float v = 0.0f;
        for (int d = 0; d < deg; ++d) {
            int w = fbin - s_flo4[d];
            if (w >= 0 && w < s_nz4[d])
                v += g_Weff[((size_t)s_k[d]*KeW + 4*w + c)*KeW + 4*s_wp[d] + c2];
        }
        g_M[((size_t)f*MW + j)*16 + cc] = v;
    }
    if (threadIdx.x < 4) {
        float v = 0.0f;
        for (int d = 0; d < deg; ++d)
            v += g_beff[s_k[d]*KEMAX + 4*s_wp[d] + threadIdx.x];
        g_bias[f*4 + threadIdx.x] = v;
    }
}

// ---------------------------------------------------------------------------
// k_main: block = 32 rows x 16 f'. warp = 32 lanes(1 row) x 1 f'-pair.
// 3 blocks/SM (24 warps) for latency hiding. smo padded (stride 69/17)
// to kill the 32-way bank conflict in the epilogue.
// ---------------------------------------------------------------------------
__global__ __launch_bounds__(256, 3) void k_main(
    const float* __restrict__ x, float* __restrict__ out, int xrange, int xw)
{
    extern __shared__ __align__(16) float4 smx[];          // [32][xw]
    float* smo = reinterpret_cast<float*>(smx + 32*xw);    // [32][69]

    const int tid   = threadIdx.x;
    const int f0    = blockIdx.x * 16;
    const int p0    = f0 >> 1;
    const int row0  = blockIdx.y * 32;
    const int fbase = g_fmin2[p0];

    for (int e = tid; e < 32*xrange; e += 256) {
        int u = e % xrange, r = e / xrange;
        int f = min(fbase + u, Ff-1);
        int row = row0 + r, b = row >> 9, t = row & 511;
        const float* xp = x + ((size_t)(b*4)*512 + t)*Ff + f;
        smx[r*xw + u] = make_float4(xp[0], xp[CSTR], xp[(size_t)2*CSTR], xp[(size_t)3*CSTR]);
    }
    __syncthreads();

    const int wrp = tid >> 5, lane = tid & 31;
    const int p    = p0 + wrp;
    const int jmax = g_wid2[p];
    const int u0   = g_fmin2[p] - fbase;
    const int fA   = 2*p;

    const ulonglong2* mA = reinterpret_cast<const ulonglong2*>(g_M + (size_t)fA*MW*16);
    const ulonglong2* mB = reinterpret_cast<const ulonglong2*>(g_M + (size_t)(fA+1)*MW*16);
    ulonglong2 bAv = *reinterpret_cast<const ulonglong2*>(&g_bias[fA*4]);
    ulonglong2 bBv = *reinterpret_cast<const ulonglong2*>(&g_bias[(fA+1)*4]);

    ull acc[2][2];
    acc[0][0] = bAv.x; acc[0][1] = bAv.y;
    acc[1][0] = bBv.x; acc[1][1] = bBv.y;

    const float4* xp = smx + lane*xw + u0;

    #pragma unroll 2
    for (int j = 0; j < jmax; ++j) {
        float4 xa = xp[j];
        ulonglong2 a0 = mA[j*4+0], a1 = mA[j*4+1], a2 = mA[j*4+2], a3 = mA[j*4+3];
        ulonglong2 c0 = mB[j*4+0], c1 = mB[j*4+1], c2v = mB[j*4+2], c3 = mB[j*4+3];
        ull s;
        s = splat2(xa.x);
        ffma2(acc[0][0], s, a0.x); ffma2(acc[0][1], s, a0.y);
        ffma2(acc[1][0], s, c0.x); ffma2(acc[1][1], s, c0.y);
        s = splat2(xa.y);
        ffma2(acc[0][0], s, a1.x); ffma2(acc[0][1], s, a1.y);
        ffma2(acc[1][0], s, c1.x); ffma2(acc[1][1], s, c1.y);
        s = splat2(xa.z);
        ffma2(acc[0][0], s, a2.x); ffma2(acc[0][1], s, a2.y);
        ffma2(acc[1][0], s, c2v.x); ffma2(acc[1][1], s, c2v.y);
        s = splat2(xa.w);
        ffma2(acc[0][0], s, a3.x); ffma2(acc[0][1], s, a3.y);
        ffma2(acc[1][0], s, c3.x); ffma2(acc[1][1], s, c3.y);
    }

    #pragma unroll
    for (int g = 0; g < 2; ++g) {
        int fx = 2*wrp + g;
        float v0,v1,v2,v3;
        unpack2(acc[g][0], v0, v1);
        unpack2(acc[g][1], v2, v3);
        smo[lane*69 + 0*17 + fx] = v0;
        smo[lane*69 + 1*17 + fx] = v1;
        smo[lane*69 + 2*17 + fx] = v2;
        smo[lane*69 + 3*17 + fx] = v3;
    }
    __syncthreads();

    for (int e = tid; e < 2048; e += 256) {
        int fx = e & 15, cc2 = (e >> 4) & 3, r = e >> 6;
        int f = f0 + fx;
        if (f < Ff) {
            int row = row0 + r, b = row >> 9, t = row & 511;
            out[((size_t)(b*4 + cc2)*512 + t)*Ff + f] = smo[r*69 + cc2*17 + fx];
        }
    }
}

// ---------------------------------------------------------------------------
extern "C" void kernel_launch(void* const* d_in, const int* in_sizes, int n_in,
                              void* d_out, int out_size)
{
    const float* x     = (const float*)d_in[0];
    const float* W1    = (const float*)d_in[1];
    const float* b1    = (const float*)d_in[2];
    const float* W2    = (const float*)d_in[3];
    const float* b2    = (const float*)d_in[4];
    const int*   nzidx = (const int*)  d_in[5];
    const float* nzmel = (const float*)d_in[6];
    const float* mask  = (const float*)d_in[7];
    const float* ola   = (const float*)d_in[8];

    const int Wb = in_sizes[5] / Kb;

    k_bands<<<1, 256>>>(nzidx, mask, Wb);
    k_finfo<<<33, 256>>>();

    int gy = (4*Wb + 15) / 16;
    k_weff<<<dim3(Kb, gy), 256>>>(W1, b1, W2, b2, nzidx, nzmel, ola, Wb);

    k_scatter<<<NFP, 256>>>(Wb);

    int xrange = 2*Wb + 16;
    int xw = xrange | 1;
    int main_smem = 32*xw*(int)sizeof(float4) + 32*69*(int)sizeof(float);
    cudaFuncSetAttribute(k_main, cudaFuncAttributeMaxDynamicSharedMemorySize, main_smem);
    k_main<<<dim3((Ff + 15)/16, NROWS/32), 256, main_smem>>>(x, (float*)d_out, xrange, xw);
}

// round 6
// speedup vs baseline: 1.5481x; 1.0348x over previous
#include <cuda_runtime.h>
#include <stdint.h>

#define Kb     256
#define Dd     128
#define KEMAX  256
#define Ff     1025
#define NROWS  1024
#define CSTR   (512*1025)
#define MW     96
#define NFP    1056
#define NPAIR  528
#define NBCOL  68

typedef unsigned long long ull;

// ---- static device scratch ----
__device__ float g_Weff[(size_t)Kb*KEMAX*KEMAX];
__device__ float g_beff[Kb*KEMAX];
__device__ int   g_flo[Kb], g_nz[Kb];
__device__ int   g_deg[NFP], g_bands[NFP*4];
__device__ int   g_fmin2[NPAIR], g_wid2[NPAIR];
__device__ int   g_bmin[NBCOL], g_bwid[NBCOL];
__device__ float g_M[(size_t)NFP*MW*16];   // [f'][j][c][c2]
__device__ float g_bias[NFP*4];

__device__ __forceinline__ ull splat2(float v) {
    ull r; asm("mov.b64 %0, {%1, %1};" : "=l"(r) : "f"(v)); return r;
}
__device__ __forceinline__ void ffma2(ull& d, ull a, ull b) {
    asm("fma.rn.f32x2 %0, %1, %2, %0;" : "+l"(d) : "l"(a), "l"(b));
}
__device__ __forceinline__ void unpack2(ull v, float& lo, float& hi) {
    asm("mov.b64 {%0, %1}, %2;" : "=f"(lo), "=f"(hi) : "l"(v));
}

// ---------------------------------------------------------------------------
__global__ __launch_bounds__(256) void k_bands(
    const int* __restrict__ nzidx, const float* __restrict__ mask, int Wb)
{
    const int k = threadIdx.x;
    int n = 0;
    for (int w = 0; w < Wb; ++w) n += (mask[k*Wb + w] > 0.5f);
    g_flo[k] = nzidx[k*Wb];
    g_nz[k]  = n;
}

// ---------------------------------------------------------------------------
// k_finfo: per-f' band list; per-pair [fmin,width); per-block-col [bmin,bwid).
// ---------------------------------------------------------------------------
__global__ __launch_bounds__(256) void k_finfo()
{
    __shared__ int s_flo[Kb], s_nz[Kb];
    __shared__ int s_fmf[32], s_fxf[32];
    __shared__ int s_pmn[16], s_pwd[16];
    const int tid = threadIdx.x;
    s_flo[tid] = g_flo[tid];
    s_nz[tid]  = g_nz[tid];
    __syncthreads();

    if (tid < 32) {
        int f = blockIdx.x*32 + tid;
        int deg = 0, bl[4] = {0,0,0,0};
        int fmn = 1<<29, fmx = -1;
        if (f < Ff) {
            for (int k = 0; k < Kb; ++k) {
                int w = f - s_flo[k];
                if (w >= 0 && w < s_nz[k]) {
                    if (deg < 4) bl[deg] = k;
                    ++deg;
                    fmn = min(fmn, s_flo[k]);
                    fmx = max(fmx, s_flo[k] + s_nz[k]);
                }
            }
        }
        deg = min(deg, 4);
        if (f < NFP) {
            g_deg[f] = deg;
            #pragma unroll
            for (int i = 0; i < 4; ++i) g_bands[f*4+i] = bl[i];
        }
        s_fmf[tid] = deg ? fmn : (1<<29);
        s_fxf[tid] = deg ? fmx : -1;
    }
    __syncthreads();
    if (tid < 16) {
        int p = blockIdx.x*16 + tid;
        int fmn = min(s_fmf[2*tid], s_fmf[2*tid+1]);
        int fmx = max(s_fxf[2*tid], s_fxf[2*tid+1]);
        int w;
        if (fmx < 0) { fmn = 0; w = 0; }
        else         { w = min(fmx - fmn, MW); }
        if (p < NPAIR) { g_fmin2[p] = fmn; g_wid2[p] = w; }
        s_pmn[tid] = fmn; s_pwd[tid] = w;
    }
    __syncthreads();
    if (tid < 2) {
        int bc = blockIdx.x*2 + tid;
        int mn = 1<<29, mx = -1;
        #pragma unroll
        for (int i = 0; i < 8; ++i) {
            int pl = tid*8 + i;
            if (s_pwd[pl] > 0) {
                mn = min(mn, s_pmn[pl]);
                mx = max(mx, s_pmn[pl] + s_pwd[pl]);
            }
        }
        if (bc < NBCOL) {
            if (mx < 0) { g_bmin[bc] = 0; g_bwid[bc] = 0; }
            else        { g_bmin[bc] = mn; g_bwid[bc] = mx - mn; }
        }
    }
}

// ---------------------------------------------------------------------------
// k_weff: per-band fused W1@W2 (mel, 1/ola folded). grid (Kb, itiles of 16).
// ---------------------------------------------------------------------------
__global__ __launch_bounds__(256) void k_weff(
    const float* __restrict__ W1, const float* __restrict__ b1,
    const float* __restrict__ W2, const float* __restrict__ b2,
    const int*   __restrict__ nzidx, const float* __restrict__ nzmel,
    const float* __restrict__ ola, int Wb)
{
    __shared__ float W1s[16*Dd];
    __shared__ float cs[KEMAX];
    __shared__ float rs[16];
    __shared__ float b1s[Dd];

    const int k     = blockIdx.x;
    const int KeW   = 4*Wb;
    const int iBase = blockIdx.y * 16;
    const int tid   = threadIdx.x;

    const int nnz = g_nz[k];
    const int Ke4 = 4*nnz;
    if (iBase >= Ke4) return;
    const int ni = min(16, Ke4 - iBase);

    for (int j = tid; j < ni*Dd; j += 256)
        W1s[j] = W1[((size_t)k*KeW + iBase)*Dd + j];
    for (int w = tid; w < nnz; w += 256) {
        float inv = 1.0f / ola[nzidx[k*Wb + w]];
        cs[4*w+0]=inv; cs[4*w+1]=inv; cs[4*w+2]=inv; cs[4*w+3]=inv;
    }
    if (tid < ni) rs[tid] = nzmel[k*Wb + ((iBase + tid) >> 2)];
    if (tid < Dd) b1s[tid] = b1[k*Dd + tid];
    __syncthreads();

    const int nct = Ke4 >> 2, nrt = ni >> 2;
    if (tid < nrt*nct) {
        const int tr = tid / nct, tc = tid - tr*nct;
        ull acc[4][2] = {{0,0},{0,0},{0,0},{0,0}};
        const float* a = &W1s[(tr*4)*Dd];
        const float* w2base = W2 + (size_t)k*Dd*KeW + tc*4;
        #pragma unroll 4
        for (int d = 0; d < Dd; ++d) {
            ulonglong2 bv = *reinterpret_cast<const ulonglong2*>(w2base + (size_t)d*KeW);
            ull s;
            s = splat2(a[d]);      ffma2(acc[0][0], s, bv.x); ffma2(acc[0][1], s, bv.y);
            s = splat2(a[Dd+d]);   ffma2(acc[1][0], s, bv.x); ffma2(acc[1][1], s, bv.y);
            s = splat2(a[2*Dd+d]); ffma2(acc[2][0], s, bv.x); ffma2(acc[2][1], s, bv.y);
            s = splat2(a[3*Dd+d]); ffma2(acc[3][0], s, bv.x); ffma2(acc[3][1], s, bv.y);
        }
        const int gi = iBase + tr*4, go = tc*4;
        float4 c4 = *reinterpret_cast<const float4*>(&cs[go]);
        #pragma unroll
        for (int rr = 0; rr < 4; ++rr) {
            float v0,v1,v2,v3;
            unpack2(acc[rr][0], v0, v1);
            unpack2(acc[rr][1], v2, v3);
            float r = rs[tr*4+rr];
            float4 o4 = make_float4(v0*r*c4.x, v1*r*c4.y, v2*r*c4.z, v3*r*c4.w);
            *reinterpret_cast<float4*>(&g_Weff[((size_t)k*KeW + gi+rr)*KeW + go]) = o4;
        }
    }

    if (blockIdx.y == 0) {
        for (int o = tid; o < Ke4; o += 256) {
            float s = b2[(size_t)k*KeW + o];
            for (int d = 0; d < Dd; ++d) s += b1s[d] * W2[((size_t)k*Dd + d)*KeW + o];
            g_beff[k*KEMAX + o] = s * cs[o];
        }
    }
}

// ---------------------------------------------------------------------------
// k_scatter: assemble banded rows of M, float4 over contiguous c2.
// ---------------------------------------------------------------------------
__global__ __launch_bounds__(256) void k_scatter(int Wb)
{
    const int f   = blockIdx.x;
    const int KeW = 4*Wb;
    const int p   = f >> 1;
    const int fm2 = g_fmin2[p];
    const int wid = g_wid2[p];
    const int deg = g_deg[f];
    __shared__ int s_k[4], s_flo4[4], s_nz4[4], s_wp[4];
    if (threadIdx.x < 4) {
        int k = g_bands[f*4 + threadIdx.x];
        s_k[threadIdx.x]    = k;
        s_flo4[threadIdx.x] = g_flo[k];
        s_nz4[threadIdx.x]  = g_nz[k];
        s_wp[threadIdx.x]   = f - g_flo[k];
    }
    __syncthreads();

    for (int pos = threadIdx.x; pos < wid*4; pos += 256) {
        int j = pos >> 2;
        int c = pos & 3;
        int fbin = fm2 + j;
        float4 v = make_float4(0.f, 0.f, 0.f, 0.f);
        for (int d = 0; d < deg; ++d) {
            int w = fbin - s_flo4[d];
            if (w >= 0 && w < s_nz4[d]) {
                float4 u = *reinterpret_cast<const float4*>(
                    &g_Weff[((size_t)s_k[d]*KeW + 4*w + c)*KeW + 4*s_wp[d]]);
                v.x += u.x; v.y += u.y; v.z += u.z; v.w += u.w;
            }
        }
        *reinterpret_cast<float4*>(&g_M[((size_t)f*MW + j)*16 + c*4]) = v;
    }
    if (threadIdx.x < 4) {
        float v = 0.0f;
        for (int d = 0; d < deg; ++d)
            v += g_beff[s_k[d]*KEMAX + 4*s_wp[d] + threadIdx.x];
        g_bias[f*4 + threadIdx.x] = v;
    }
}

// ---------------------------------------------------------------------------
// k_main: block = 32 rows x 16 f'; warp = 32 lanes(rows) x 1 f'-pair.
// 4 blocks/SM; dynamic x window; smo aliases smx.
// ---------------------------------------------------------------------------
__global__ __launch_bounds__(256, 4) void k_main(
    const float* __restrict__ x, float* __restrict__ out, int xw)
{
    extern __shared__ __align__(16) float4 smx[];          // [32][xw]
    float* smo = reinterpret_cast<float*>(smx);            // aliases smx

    const int tid   = threadIdx.x;
    const int f0    = blockIdx.x * 16;
    const int p0    = f0 >> 1;
    const int row0  = blockIdx.y * 32;
    const int bmin  = g_bmin[blockIdx.x];
    const int bwid  = g_bwid[blockIdx.x];

    for (int e = tid; e < 32*bwid; e += 256) {
        int u = e % bwid, r = e / bwid;
        int f = min(bmin + u, Ff-1);
        int row = row0 + r, b = row >> 9, t = row & 511;
        const float* xp = x + ((size_t)(b*4)*512 + t)*Ff + f;
        smx[r*xw + u] = make_float4(xp[0], xp[CSTR], xp[(size_t)2*CSTR], xp[(size_t)3*CSTR]);
    }
    __syncthreads();

    const int wrp = tid >> 5, lane = tid & 31;
    const int p    = p0 + wrp;
    const int jmax = g_wid2[p];
    const int u0   = g_fmin2[p] - bmin;
    const int fA   = 2*p;

    const ulonglong2* mA = reinterpret_cast<const ulonglong2*>(g_M + (size_t)fA*MW*16);
    const ulonglong2* mB = reinterpret_cast<const ulonglong2*>(g_M + (size_t)(fA+1)*MW*16);
    ulonglong2 bAv = *reinterpret_cast<const ulonglong2*>(&g_bias[fA*4]);
    ulonglong2 bBv = *reinterpret_cast<const ulonglong2*>(&g_bias[(fA+1)*4]);

    ull acc[2][2];
    acc[0][0] = bAv.x; acc[0][1] = bAv.y;
    acc[1][0] = bBv.x; acc[1][1] = bBv.y;

    const float4* xp = smx + lane*xw + u0;

    #pragma unroll 2
    for (int j = 0; j < jmax; ++j) {
        float4 xa = xp[j];
        ull sx = splat2(xa.x), sy = splat2(xa.y), sz = splat2(xa.z), sw = splat2(xa.w);
        {
            ulonglong2 a0 = mA[j*4+0], a1 = mA[j*4+1], a2 = mA[j*4+2], a3 = mA[j*4+3];
            ffma2(acc[0][0], sx, a0.x); ffma2(acc[0][1], sx, a0.y);
            ffma2(acc[0][0], sy, a1.x); ffma2(acc[0][1], sy, a1.y);
            ffma2(acc[0][0], sz, a2.x); ffma2(acc[0][1], sz, a2.y);
            ffma2(acc[0][0], sw, a3.x); ffma2(acc[0][1], sw, a3.y);
        }
        {
            ulonglong2 c0 = mB[j*4+0], c1 = mB[j*4+1], c2v = mB[j*4+2], c3 = mB[j*4+3];
            ffma2(acc[1][0], sx, c0.x); ffma2(acc[1][1], sx, c0.y);
            ffma2(acc[1][0], sy, c1.x); ffma2(acc[1][1], sy, c1.y);
            ffma2(acc[1][0], sz, c2v.x); ffma2(acc[1][1], sz, c2v.y);
            ffma2(acc[1][0], sw, c3.x); ffma2(acc[1][1], sw, c3.y);
        }
    }

    __syncthreads();   // x tile dead; smo aliases smx

    #pragma unroll
    for (int g = 0; g < 2; ++g) {
        int fx = 2*wrp + g;
        float v0,v1,v2,v3;
        unpack2(acc[g][0], v0, v1);
        unpack2(acc[g][1], v2, v3);
        smo[lane*69 + 0*17 + fx] = v0;
        smo[lane*69 + 1*17 + fx] = v1;
        smo[lane*69 + 2*17 + fx] = v2;
        smo[lane*69 + 3*17 + fx] = v3;
    }
    __syncthreads();

    for (int e = tid; e < 2048; e += 256) {
        int fx = e & 15, cc2 = (e >> 4) & 3, r = e >> 6;
        int f = f0 + fx;
        if (f < Ff) {
            int row = row0 + r, b = row >> 9, t = row & 511;
            out[((size_t)(b*4 + cc2)*512 + t)*Ff + f] = smo[r*69 + cc2*17 + fx];
        }
    }
}

// ---------------------------------------------------------------------------
extern "C" void kernel_launch(void* const* d_in, const int* in_sizes, int n_in,
                              void* d_out, int out_size)
{
    const float* x     = (const float*)d_in[0];
    const float* W1    = (const float*)d_in[1];
    const float* b1    = (const float*)d_in[2];
    const float* W2    = (const float*)d_in[3];
    const float* b2    = (const float*)d_in[4];
    const int*   nzidx = (const int*)  d_in[5];
    const float* nzmel = (const float*)d_in[6];
    const float* mask  = (const float*)d_in[7];
    const float* ola   = (const float*)d_in[8];

    const int Wb = in_sizes[5] / Kb;

    k_bands<<<1, 256>>>(nzidx, mask, Wb);
    k_finfo<<<33, 256>>>();

    int gy = (4*Wb + 15) / 16;
    k_weff<<<dim3(Kb, gy), 256>>>(W1, b1, W2, b2, nzidx, nzmel, ola, Wb);

    k_scatter<<<NFP, 256>>>(Wb);

    int xrange = 2*Wb + 16;
    int xw = xrange | 1;
    int main_smem = 32*xw*(int)sizeof(float4);
    if (main_smem < 32*69*(int)sizeof(float)) main_smem = 32*69*(int)sizeof(float);
    cudaFuncSetAttribute(k_main, cudaFuncAttributeMaxDynamicSharedMemorySize, main_smem);
    k_main<<<dim3((Ff + 15)/16, NROWS/32), 256, main_smem>>>(x, (float*)d_out, xw);
}